// round 1
// baseline (speedup 1.0000x reference)
#include <cuda_runtime.h>
#include <math.h>

#define B_ROWS 2048
#define D_DIM  512
#define W_DIM  512
#define N_LEAF 64
#define N_NODE 63

#define BM 64
#define BN 64
#define BK 32

// Scratch for the soft bin distribution [B, 64] (no cudaMalloc allowed).
__device__ float g_dist[B_ROWS * N_LEAF];

__device__ __forceinline__ float sigmoidf(float z) {
    return 1.0f / (1.0f + expf(-z));
}

// ---------------------------------------------------------------------------
// Kernel 1: angles -> decisions -> leaf distribution.  One warp per row.
// ---------------------------------------------------------------------------
__global__ void __launch_bounds__(256) dist_kernel(
    const float* __restrict__ x,
    const float* __restrict__ ray,
    const float* __restrict__ w_i,
    const float* __restrict__ b_i,
    const float* __restrict__ a_i,
    const int*   __restrict__ idx)
{
    __shared__ float sray[D_DIM];
    __shared__ float sdec[8][64];

    const int tid = threadIdx.x;
    for (int i = tid; i < D_DIM; i += 256) sray[i] = ray[i];
    __syncthreads();

    const int warp = tid >> 5;
    const int lane = tid & 31;
    const int row  = blockIdx.x * 8 + warp;

    const float* xr = x + (size_t)row * D_DIM;
    float dot = 0.f, ss = 0.f, rss = 0.f;
#pragma unroll
    for (int j = 0; j < 4; j++) {
        float4 xv = reinterpret_cast<const float4*>(xr)[lane + 32 * j];
        float4 rv = reinterpret_cast<const float4*>(sray)[lane + 32 * j];
        dot += xv.x * rv.x + xv.y * rv.y + xv.z * rv.z + xv.w * rv.w;
        ss  += xv.x * xv.x + xv.y * xv.y + xv.z * xv.z + xv.w * xv.w;
        rss += rv.x * rv.x + rv.y * rv.y + rv.z * rv.z + rv.w * rv.w;
    }
#pragma unroll
    for (int o = 16; o > 0; o >>= 1) {
        dot += __shfl_xor_sync(0xffffffffu, dot, o);
        ss  += __shfl_xor_sync(0xffffffffu, ss,  o);
        rss += __shfl_xor_sync(0xffffffffu, rss, o);
    }
    float xn = fmaxf(sqrtf(ss),  1e-8f);
    float rn = fmaxf(sqrtf(rss), 1e-8f);
    float c  = dot / (xn * rn);
    c = fminf(fmaxf(c, -1.0f), 1.0f);
    const float angle = acosf(c) * 0.3183098861837907f;  // / pi

    // 63 inner-node decision probabilities
    for (int n = lane; n < N_NODE; n += 32) {
        float nf = (0.5f + sigmoidf(w_i[n])) * angle - sigmoidf(b_i[n]);
        sdec[warp][n] = sigmoidf(nf * (1.0f + a_i[n]));
    }
    __syncwarp();

    // 64 leaves: product of 6 gathered factors (idx < 63 -> dec, else 1-dec)
    for (int leaf = lane; leaf < N_LEAF; leaf += 32) {
        float p = 1.0f;
#pragma unroll
        for (int t = 0; t < 6; t++) {
            int j = idx[leaf * 6 + t];
            float v = (j < N_NODE) ? sdec[warp][j] : (1.0f - sdec[warp][j - N_NODE]);
            p *= v;
        }
        g_dist[row * N_LEAF + leaf] = p;
    }
}

// ---------------------------------------------------------------------------
// Kernel 2: out[b,w] = sum_l d[b,l] * sum_i x[b,i] * T[l,i,w]
// fp32 register-tiled GEMM: BM=64, BN=64, BK=32, 128 thr, TM=8 x TN=4.
// x-tile loaded once per k-block (reused across all 64 leaves); per-leaf
// partial accumulators scaled by d[row,l] in a cheap epilogue.
// B-tile (T) double-buffered to hide global-load latency.
// ---------------------------------------------------------------------------
__global__ void __launch_bounds__(128) gemm_kernel(
    const float* __restrict__ x,
    const float* __restrict__ T,
    float* __restrict__ out)
{
    __shared__ float Xs[BK][BM];          // 8 KB   (x tile, transposed)
    __shared__ float Bs[2][BK][BN];       // 16 KB  (T tile, double buffered)
    __shared__ float Dt[BM][N_LEAF];      // 16 KB  (distribution tile)

    const int tid = threadIdx.x;
    const int m0 = blockIdx.y * BM;
    const int n0 = blockIdx.x * BN;

    // Load distribution tile [BM x 64]
#pragma unroll
    for (int i = 0; i < 8; i++) {
        int id = tid + i * 128;            // 0..1023 float4s
        int m = id >> 4, lq = id & 15;
        float4 v = reinterpret_cast<const float4*>(g_dist + (size_t)(m0 + m) * N_LEAF)[lq];
        reinterpret_cast<float4*>(&Dt[m][0])[lq] = v;
    }

    const int tx = tid & 15;   // -> 4 output cols  (tx*4)
    const int ty = tid >> 4;   // -> 8 output rows  (ty*8)

    float oacc[8][4];
#pragma unroll
    for (int i = 0; i < 8; i++)
#pragma unroll
        for (int j = 0; j < 4; j++) oacc[i][j] = 0.f;

    float4 pf[4];

    // Prologue: prefetch B tile for (kb=0, l=0) into buffer 0
#pragma unroll
    for (int i = 0; i < 4; i++) {
        int id = tid + i * 128;
        int k = id >> 4, wq = id & 15;
        pf[i] = *reinterpret_cast<const float4*>(T + ((size_t)0 * D_DIM + 0 + k) * W_DIM + n0 + wq * 4);
    }
#pragma unroll
    for (int i = 0; i < 4; i++) {
        int id = tid + i * 128;
        int k = id >> 4, wq = id & 15;
        *reinterpret_cast<float4*>(&Bs[0][k][wq * 4]) = pf[i];
    }

    // Flattened loop: it = kb_block*64 + l  (l fastest so x-tile is reused)
    for (int it = 0; it < (D_DIM / BK) * N_LEAF; ++it) {
        const int l  = it & 63;
        const int kb = (it >> 6) << 5;
        const int buf = it & 1;

        if (l == 0) {
            // New k-block: refill the x tile (previous compute finished at the
            // trailing __syncthreads of the prior iteration).
#pragma unroll
            for (int i = 0; i < 4; i++) {
                int id = tid + i * 128;
                int kq = id >> 6, m = id & 63;
                float4 v = *reinterpret_cast<const float4*>(
                    x + (size_t)(m0 + m) * D_DIM + kb + kq * 4);
                Xs[kq * 4 + 0][m] = v.x;
                Xs[kq * 4 + 1][m] = v.y;
                Xs[kq * 4 + 2][m] = v.z;
                Xs[kq * 4 + 3][m] = v.w;
            }
            __syncthreads();  // Xs (and pending Bs sts) visible
        }

        // Prefetch next iteration's B tile (global -> regs), latency hidden by compute
        const int nit = it + 1;
        const bool has_next = (nit < (D_DIM / BK) * N_LEAF);
        if (has_next) {
            const int nl  = nit & 63;
            const int nkb = (nit >> 6) << 5;
            const float* tb = T + ((size_t)nl * D_DIM + nkb) * W_DIM + n0;
#pragma unroll
            for (int i = 0; i < 4; i++) {
                int id = tid + i * 128;
                int k = id >> 4, wq = id & 15;
                pf[i] = *reinterpret_cast<const float4*>(tb + (size_t)k * W_DIM + wq * 4);
            }
        }

        // Compute: pacc = Xs^T(8 rows) * Bs(4 cols) over 32 k-steps
        float pacc[8][4];
#pragma unroll
        for (int i = 0; i < 8; i++)
#pragma unroll
            for (int j = 0; j < 4; j++) pacc[i][j] = 0.f;

#pragma unroll
        for (int k = 0; k < BK; k++) {
            float4 a0 = *reinterpret_cast<const float4*>(&Xs[k][ty * 8]);
            float4 a1 = *reinterpret_cast<const float4*>(&Xs[k][ty * 8 + 4]);
            float4 bv = *reinterpret_cast<const float4*>(&Bs[buf][k][tx * 4]);
            float a[8] = {a0.x, a0.y, a0.z, a0.w, a1.x, a1.y, a1.z, a1.w};
            float bb[4] = {bv.x, bv.y, bv.z, bv.w};
#pragma unroll
            for (int i = 0; i < 8; i++)
#pragma unroll
                for (int j = 0; j < 4; j++)
                    pacc[i][j] = fmaf(a[i], bb[j], pacc[i][j]);
        }

        // Scale by this leaf's weight per row and accumulate
#pragma unroll
        for (int i = 0; i < 8; i++) {
            float ds = Dt[ty * 8 + i][l];
#pragma unroll
            for (int j = 0; j < 4; j++)
                oacc[i][j] = fmaf(ds, pacc[i][j], oacc[i][j]);
        }

        // Store the prefetched tile into the other buffer (safe: that buffer
        // was last read in iteration it-1, fenced by its trailing sync)
        if (has_next) {
#pragma unroll
            for (int i = 0; i < 4; i++) {
                int id = tid + i * 128;
                int k = id >> 4, wq = id & 15;
                *reinterpret_cast<float4*>(&Bs[buf ^ 1][k][wq * 4]) = pf[i];
            }
        }
        __syncthreads();
    }

    // Write output tile
#pragma unroll
    for (int i = 0; i < 8; i++) {
        float4 v = make_float4(oacc[i][0], oacc[i][1], oacc[i][2], oacc[i][3]);
        *reinterpret_cast<float4*>(out + (size_t)(m0 + ty * 8 + i) * W_DIM + n0 + tx * 4) = v;
    }
}

// ---------------------------------------------------------------------------
extern "C" void kernel_launch(void* const* d_in, const int* in_sizes, int n_in,
                              void* d_out, int out_size)
{
    const float* x   = (const float*)d_in[0];  // [2048, 512]
    const float* ray = (const float*)d_in[1];  // [1, 512]
    const float* w_i = (const float*)d_in[2];  // [1, 63]
    const float* b_i = (const float*)d_in[3];  // [1, 63]
    const float* a_i = (const float*)d_in[4];  // [1, 63]
    const float* T   = (const float*)d_in[5];  // [64, 512, 512]
    const int*   idx = (const int*)d_in[6];    // [64, 6]
    float* out = (float*)d_out;                // [2048, 512]

    dist_kernel<<<B_ROWS / 8, 256>>>(x, ray, w_i, b_i, a_i, idx);

    dim3 grid(W_DIM / BN, B_ROWS / BM);  // (8, 32) = 256 CTAs
    gemm_kernel<<<grid, 128>>>(x, T, out);
}

// round 3
// speedup vs baseline: 3.1708x; 3.1708x over previous
#include <cuda_runtime.h>
#include <cuda_bf16.h>
#include <math.h>
#include <stdint.h>

#define B_ROWS 2048
#define D_DIM  512
#define W_DIM  512
#define N_LEAF 64
#define N_NODE 63

// ---------------------------------------------------------------------------
// Device scratch (no cudaMalloc allowed)
// ---------------------------------------------------------------------------
__device__ float g_dist[B_ROWS * N_LEAF];
__device__ __nv_bfloat16 g_Thi[(size_t)N_LEAF * D_DIM * W_DIM];  // [l][w][i] K-major
__device__ __nv_bfloat16 g_Tlo[(size_t)N_LEAF * D_DIM * W_DIM];

// ---------------------------------------------------------------------------
// Helpers
// ---------------------------------------------------------------------------
__device__ __forceinline__ uint32_t smem_u32(const void* p) {
    uint32_t a;
    asm("{ .reg .u64 t; cvta.to.shared.u64 t, %1; cvt.u32.u64 %0, t; }"
        : "=r"(a) : "l"(p));
    return a;
}

__device__ __forceinline__ uint32_t pack_bf2(__nv_bfloat16 a, __nv_bfloat16 b) {
    __nv_bfloat162 t = __halves2bfloat162(a, b);
    return *reinterpret_cast<uint32_t*>(&t);
}

__device__ __forceinline__ float sigmoidf_(float z) { return 1.0f / (1.0f + expf(-z)); }

__device__ __forceinline__ void ldsm4(uint32_t addr, uint32_t r[4]) {
    asm volatile("ldmatrix.sync.aligned.m8n8.x4.shared.b16 {%0,%1,%2,%3}, [%4];"
                 : "=r"(r[0]), "=r"(r[1]), "=r"(r[2]), "=r"(r[3]) : "r"(addr));
}

__device__ __forceinline__ void mma_bf16(float c[4], const uint32_t a[4], const uint32_t* b) {
    asm volatile("mma.sync.aligned.m16n8k16.row.col.f32.bf16.bf16.f32 "
                 "{%0,%1,%2,%3}, {%4,%5,%6,%7}, {%8,%9}, {%0,%1,%2,%3};"
                 : "+f"(c[0]), "+f"(c[1]), "+f"(c[2]), "+f"(c[3])
                 : "r"(a[0]), "r"(a[1]), "r"(a[2]), "r"(a[3]), "r"(b[0]), "r"(b[1]));
}

#define CP_ASYNC16(dst, src) \
    asm volatile("cp.async.cg.shared.global [%0], [%1], 16;" :: "r"(dst), "l"(src))
#define CP_COMMIT() asm volatile("cp.async.commit_group;" ::: "memory")
#define CP_WAIT0()  asm volatile("cp.async.wait_group 0;" ::: "memory")

// ---------------------------------------------------------------------------
// Kernel 0: transpose + bf16 hi/lo split of T:  [l][i][w] fp32 -> [l][w][i] bf16
// ---------------------------------------------------------------------------
__global__ void __launch_bounds__(256) convert_kernel(const float* __restrict__ T) {
    __shared__ float tile[64][65];
    const int tid = threadIdx.x;
    const int l  = blockIdx.z;
    const int i0 = blockIdx.y * 64;
    const int w0 = blockIdx.x * 64;

    const float* tp = T + ((size_t)l * D_DIM + i0) * W_DIM + w0;
#pragma unroll
    for (int e = 0; e < 16; e++) {
        int id = tid + e * 256;
        int ii = id >> 6, ww = id & 63;
        tile[ii][ww] = tp[(size_t)ii * W_DIM + ww];
    }
    __syncthreads();
#pragma unroll
    for (int e = 0; e < 16; e++) {
        int id = tid + e * 256;
        int ww = id >> 6, ii = id & 63;
        float v = tile[ii][ww];
        __nv_bfloat16 h  = __float2bfloat16_rn(v);
        __nv_bfloat16 lo = __float2bfloat16_rn(v - __bfloat162float(h));
        size_t o = ((size_t)l * W_DIM + (w0 + ww)) * D_DIM + (i0 + ii);
        g_Thi[o] = h;
        g_Tlo[o] = lo;
    }
}

// ---------------------------------------------------------------------------
// Kernel 1: angles -> decisions -> leaf distribution.  One warp per row.
// ---------------------------------------------------------------------------
__global__ void __launch_bounds__(256) dist_kernel(
    const float* __restrict__ x, const float* __restrict__ ray,
    const float* __restrict__ w_i, const float* __restrict__ b_i,
    const float* __restrict__ a_i, const int* __restrict__ idx)
{
    __shared__ float sray[D_DIM];
    __shared__ float sdec[8][64];

    const int tid = threadIdx.x;
    for (int i = tid; i < D_DIM; i += 256) sray[i] = ray[i];
    __syncthreads();

    const int warp = tid >> 5;
    const int lane = tid & 31;
    const int row  = blockIdx.x * 8 + warp;

    const float* xr = x + (size_t)row * D_DIM;
    float dot = 0.f, ss = 0.f, rss = 0.f;
#pragma unroll
    for (int j = 0; j < 4; j++) {
        float4 xv = reinterpret_cast<const float4*>(xr)[lane + 32 * j];
        float4 rv = reinterpret_cast<const float4*>(sray)[lane + 32 * j];
        dot += xv.x * rv.x + xv.y * rv.y + xv.z * rv.z + xv.w * rv.w;
        ss  += xv.x * xv.x + xv.y * xv.y + xv.z * xv.z + xv.w * xv.w;
        rss += rv.x * rv.x + rv.y * rv.y + rv.z * rv.z + rv.w * rv.w;
    }
#pragma unroll
    for (int o = 16; o > 0; o >>= 1) {
        dot += __shfl_xor_sync(0xffffffffu, dot, o);
        ss  += __shfl_xor_sync(0xffffffffu, ss,  o);
        rss += __shfl_xor_sync(0xffffffffu, rss, o);
    }
    float xn = fmaxf(sqrtf(ss),  1e-8f);
    float rn = fmaxf(sqrtf(rss), 1e-8f);
    float c  = dot / (xn * rn);
    c = fminf(fmaxf(c, -1.0f), 1.0f);
    const float angle = acosf(c) * 0.3183098861837907f;

    for (int n = lane; n < N_NODE; n += 32) {
        float nf = (0.5f + sigmoidf_(w_i[n])) * angle - sigmoidf_(b_i[n]);
        sdec[warp][n] = sigmoidf_(nf * (1.0f + a_i[n]));
    }
    __syncwarp();

    for (int leaf = lane; leaf < N_LEAF; leaf += 32) {
        float p = 1.0f;
#pragma unroll
        for (int t = 0; t < 6; t++) {
            int j = idx[leaf * 6 + t];
            float v = (j < N_NODE) ? sdec[warp][j] : (1.0f - sdec[warp][j - N_NODE]);
            p *= v;
        }
        g_dist[row * N_LEAF + leaf] = p;
    }
}

// ---------------------------------------------------------------------------
// Kernel 2: warp-mma (HMMA) bf16-split GEMM.
// CTA: 128m x 64n, 256 threads = 8 warps (4m x 2n), warp tile 32x32.
// k processed in 4 chunks of 128; inner loop over 64 leaves with
// cp.async double-buffered B tiles; per-leaf fragment epilogue O += d*P.
// ---------------------------------------------------------------------------
#define KC 128
#define REL_XHI 0
#define REL_XLO 32768
#define REL_B   65536           // + p*32768 ; lo half at +16384
#define REL_DT  131072          // [128][65] floats = 33280 B
#define SMEM_TOTAL (131072 + 33280)

__device__ __forceinline__ void issue_b(uint32_t dstbase, int l, int kb, int n0, int tid) {
    const __nv_bfloat16* bh = g_Thi + ((size_t)l * W_DIM + n0) * D_DIM + kb;
    const __nv_bfloat16* bl = g_Tlo + ((size_t)l * W_DIM + n0) * D_DIM + kb;
#pragma unroll
    for (int e = 0; e < 4; e++) {
        int id = tid + e * 256;
        int w = id >> 4, c = id & 15;
        uint32_t dst = dstbase + w * 256 + ((c ^ (w & 7)) << 4);
        const char* sh = (const char*)(bh + (size_t)w * D_DIM + c * 8);
        const char* sl = (const char*)(bl + (size_t)w * D_DIM + c * 8);
        CP_ASYNC16(dst, sh);
        CP_ASYNC16(dst + 16384, sl);
    }
}

__global__ void __launch_bounds__(256) gemm_mma_kernel(
    const float* __restrict__ x, float* __restrict__ out)
{
    extern __shared__ char smem[];
    const uint32_t sb = smem_u32(smem);
    const int tid  = threadIdx.x;
    const int wid  = tid >> 5;
    const int lane = tid & 31;
    const int wm   = wid & 3;       // 4 m-warps
    const int wn   = wid >> 2;      // 2 n-warps
    const int m0 = blockIdx.y * 128;
    const int n0 = blockIdx.x * 64;

    float* Dt = (float*)(smem + REL_DT);   // [128][65] padded

    // Load distribution tile (128 x 64)
#pragma unroll
    for (int e = 0; e < 8; e++) {
        int id = tid + e * 256;            // 0..2047 float4s
        int r = id >> 4, q = id & 15;
        float4 v = reinterpret_cast<const float4*>(g_dist + (size_t)(m0 + r) * N_LEAF)[q];
        float* d = Dt + r * 65 + q * 4;
        d[0] = v.x; d[1] = v.y; d[2] = v.z; d[3] = v.w;
    }

    float O[2][4][4];
#pragma unroll
    for (int i = 0; i < 2; i++)
#pragma unroll
        for (int j = 0; j < 4; j++)
#pragma unroll
            for (int r = 0; r < 4; r++) O[i][j][r] = 0.f;

    const int g = lane >> 2;

    // Prologue: prefetch B(leaf 0, chunk 0) into buffer 0
    issue_b(sb + REL_B, 0, 0, n0, tid);
    CP_COMMIT();

    int p = 0;
    for (int kc = 0; kc < 4; kc++) {
        const int kb = kc * KC;
        // ---- build X hi/lo tiles [128 x 128] bf16, K-major swizzled ----
        const float* xp = x + (size_t)m0 * D_DIM + kb;
#pragma unroll 4
        for (int e = 0; e < 16; e++) {
            int id = tid + e * 256;        // 0..4095 float4s
            int m = id >> 5, q = id & 31;
            float4 v = *reinterpret_cast<const float4*>(xp + (size_t)m * D_DIM + q * 4);
            __nv_bfloat16 h0 = __float2bfloat16_rn(v.x);
            __nv_bfloat16 h1 = __float2bfloat16_rn(v.y);
            __nv_bfloat16 h2 = __float2bfloat16_rn(v.z);
            __nv_bfloat16 h3 = __float2bfloat16_rn(v.w);
            __nv_bfloat16 l0 = __float2bfloat16_rn(v.x - __bfloat162float(h0));
            __nv_bfloat16 l1 = __float2bfloat16_rn(v.y - __bfloat162float(h1));
            __nv_bfloat16 l2 = __float2bfloat16_rn(v.z - __bfloat162float(h2));
            __nv_bfloat16 l3 = __float2bfloat16_rn(v.w - __bfloat162float(h3));
            uint2 hv = make_uint2(pack_bf2(h0, h1), pack_bf2(h2, h3));
            uint2 lv = make_uint2(pack_bf2(l0, l1), pack_bf2(l2, l3));
            int off = m * 256 + (((q >> 1) ^ (m & 7)) << 4) + (q & 1) * 8;
            *reinterpret_cast<uint2*>(smem + REL_XHI + off) = hv;
            *reinterpret_cast<uint2*>(smem + REL_XLO + off) = lv;
        }
        CP_WAIT0();            // current B buffer complete (prologue / kc handoff)
        __syncthreads();       // X tiles + B buffer visible to all

        for (int l = 0; l < N_LEAF; l++) {
            // Prefetch next B tile into the other buffer (overlaps compute)
            if (l < 63)       issue_b(sb + REL_B + (p ^ 1) * 32768, l + 1, kb,       n0, tid);
            else if (kc < 3)  issue_b(sb + REL_B + (p ^ 1) * 32768, 0,     kb + KC,  n0, tid);
            CP_COMMIT();

            const uint32_t bbase = sb + REL_B + p * 32768;

            float P[2][4][4];
#pragma unroll
            for (int i = 0; i < 2; i++)
#pragma unroll
                for (int j = 0; j < 4; j++)
#pragma unroll
                    for (int r = 0; r < 4; r++) P[i][j][r] = 0.f;

#pragma unroll
            for (int ks = 0; ks < 8; ks++) {
                // A fragments (hi & lo), 2 m16 tiles each
                uint32_t ah[2][4], al[2][4];
                {
                    int row = wm * 32 + (lane & 15);
                    int ck  = ks * 2 + (lane >> 4);
#pragma unroll
                    for (int i = 0; i < 2; i++) {
                        int r2 = row + i * 16;
                        uint32_t off = r2 * 256 + ((ck ^ (r2 & 7)) << 4);
                        ldsm4(sb + REL_XHI + off, ah[i]);
                        ldsm4(sb + REL_XLO + off, al[i]);
                    }
                }
                // B fragments (hi & lo), 4 n8 frags via 2 x4 loads each
                uint32_t bh[4][2], bl[4][2];
                {
                    int row = wn * 32 + (lane & 7) + ((lane >> 4) << 3);
                    int ck  = ks * 2 + ((lane >> 3) & 1);
#pragma unroll
                    for (int j2 = 0; j2 < 2; j2++) {
                        int r2 = row + j2 * 16;
                        uint32_t off = r2 * 256 + ((ck ^ (r2 & 7)) << 4);
                        uint32_t t[4];
                        ldsm4(bbase + off, t);
                        bh[j2 * 2][0] = t[0]; bh[j2 * 2][1] = t[1];
                        bh[j2 * 2 + 1][0] = t[2]; bh[j2 * 2 + 1][1] = t[3];
                        ldsm4(bbase + 16384 + off, t);
                        bl[j2 * 2][0] = t[0]; bl[j2 * 2][1] = t[1];
                        bl[j2 * 2 + 1][0] = t[2]; bl[j2 * 2 + 1][1] = t[3];
                    }
                }
#pragma unroll
                for (int i = 0; i < 2; i++)
#pragma unroll
                    for (int j = 0; j < 4; j++) {
                        mma_bf16(P[i][j], ah[i], bh[j]);
                        mma_bf16(P[i][j], ah[i], bl[j]);
                        mma_bf16(P[i][j], al[i], bh[j]);
                    }
            }

            // Epilogue: O += d[row, l] * P
#pragma unroll
            for (int i = 0; i < 2; i++) {
                int r0 = wm * 32 + i * 16 + g;
                float d0 = Dt[r0 * 65 + l];
                float d1 = Dt[(r0 + 8) * 65 + l];
#pragma unroll
                for (int j = 0; j < 4; j++) {
                    O[i][j][0] = fmaf(d0, P[i][j][0], O[i][j][0]);
                    O[i][j][1] = fmaf(d0, P[i][j][1], O[i][j][1]);
                    O[i][j][2] = fmaf(d1, P[i][j][2], O[i][j][2]);
                    O[i][j][3] = fmaf(d1, P[i][j][3], O[i][j][3]);
                }
            }

            CP_WAIT0();        // next B buffer landed
            __syncthreads();   // safe to overwrite buf p next iteration
            p ^= 1;
        }
    }

    // Write output fragments
#pragma unroll
    for (int i = 0; i < 2; i++) {
        int r0 = m0 + wm * 32 + i * 16 + g;
#pragma unroll
        for (int j = 0; j < 4; j++) {
            int col = n0 + wn * 32 + j * 8 + 2 * (lane & 3);
            float2 v0 = make_float2(O[i][j][0], O[i][j][1]);
            float2 v1 = make_float2(O[i][j][2], O[i][j][3]);
            *reinterpret_cast<float2*>(out + (size_t)r0 * W_DIM + col)       = v0;
            *reinterpret_cast<float2*>(out + (size_t)(r0 + 8) * W_DIM + col) = v1;
        }
    }
}

// ---------------------------------------------------------------------------
extern "C" void kernel_launch(void* const* d_in, const int* in_sizes, int n_in,
                              void* d_out, int out_size)
{
    const float* x   = (const float*)d_in[0];
    const float* ray = (const float*)d_in[1];
    const float* w_i = (const float*)d_in[2];
    const float* b_i = (const float*)d_in[3];
    const float* a_i = (const float*)d_in[4];
    const float* T   = (const float*)d_in[5];
    const int*   idx = (const int*)d_in[6];
    float* out = (float*)d_out;

    cudaFuncSetAttribute(gemm_mma_kernel,
                         cudaFuncAttributeMaxDynamicSharedMemorySize, SMEM_TOTAL);

    convert_kernel<<<dim3(8, 8, 64), 256>>>(T);
    dist_kernel<<<B_ROWS / 8, 256>>>(x, ray, w_i, b_i, a_i, idx);
    gemm_mma_kernel<<<dim3(W_DIM / 64, B_ROWS / 128), 256, SMEM_TOTAL>>>(x, out);
}

// round 4
// speedup vs baseline: 3.5173x; 1.1093x over previous
#include <cuda_runtime.h>
#include <cuda_bf16.h>
#include <math.h>
#include <stdint.h>

#define B_ROWS 2048
#define D_DIM  512
#define W_DIM  512
#define N_LEAF 64
#define N_NODE 63

// ---------------------------------------------------------------------------
// Device scratch (no cudaMalloc allowed)
// ---------------------------------------------------------------------------
__device__ float g_dist[B_ROWS * N_LEAF];
__device__ float g_T[(size_t)N_LEAF * D_DIM * W_DIM];  // [l][w][i] K-major, tf32-rounded

// ---------------------------------------------------------------------------
// Helpers
// ---------------------------------------------------------------------------
__device__ __forceinline__ uint32_t smem_u32(const void* p) {
    uint32_t a;
    asm("{ .reg .u64 t; cvta.to.shared.u64 t, %1; cvt.u32.u64 %0, t; }"
        : "=r"(a) : "l"(p));
    return a;
}

__device__ __forceinline__ uint32_t to_tf32(float f) {
    uint32_t u;
    asm("cvt.rna.tf32.f32 %0, %1;" : "=r"(u) : "f"(f));
    return u;
}

__device__ __forceinline__ float sigmoidf_(float z) { return 1.0f / (1.0f + expf(-z)); }

__device__ __forceinline__ void mma_tf32(float c[4], const uint32_t a[4], const uint32_t b[2]) {
    asm volatile("mma.sync.aligned.m16n8k8.row.col.f32.tf32.tf32.f32 "
                 "{%0,%1,%2,%3}, {%4,%5,%6,%7}, {%8,%9}, {%0,%1,%2,%3};"
                 : "+f"(c[0]), "+f"(c[1]), "+f"(c[2]), "+f"(c[3])
                 : "r"(a[0]), "r"(a[1]), "r"(a[2]), "r"(a[3]), "r"(b[0]), "r"(b[1]));
}

#define CP_ASYNC16(dst, src) \
    asm volatile("cp.async.cg.shared.global [%0], [%1], 16;" :: "r"(dst), "l"(src))
#define CP_COMMIT() asm volatile("cp.async.commit_group;" ::: "memory")
#define CP_WAIT0()  asm volatile("cp.async.wait_group 0;" ::: "memory")

// ---------------------------------------------------------------------------
// Kernel 0: transpose + tf32-round T:  [l][i][w] fp32 -> [l][w][i]
// ---------------------------------------------------------------------------
__global__ void __launch_bounds__(256) convert_kernel(const float* __restrict__ T) {
    __shared__ float tile[64][65];
    const int tid = threadIdx.x;
    const int l  = blockIdx.z;
    const int i0 = blockIdx.y * 64;
    const int w0 = blockIdx.x * 64;

    const float* tp = T + ((size_t)l * D_DIM + i0) * W_DIM + w0;
#pragma unroll
    for (int e = 0; e < 16; e++) {
        int id = tid + e * 256;
        int ii = id >> 6, ww = id & 63;
        tile[ii][ww] = tp[(size_t)ii * W_DIM + ww];
    }
    __syncthreads();
#pragma unroll
    for (int e = 0; e < 16; e++) {
        int id = tid + e * 256;
        int ww = id >> 6, ii = id & 63;
        uint32_t v = to_tf32(tile[ii][ww]);
        size_t o = ((size_t)l * W_DIM + (w0 + ww)) * D_DIM + (i0 + ii);
        g_T[o] = __uint_as_float(v);
    }
}

// ---------------------------------------------------------------------------
// Kernel 1: angles -> decisions -> leaf distribution.  One warp per row.
// ---------------------------------------------------------------------------
__global__ void __launch_bounds__(256) dist_kernel(
    const float* __restrict__ x, const float* __restrict__ ray,
    const float* __restrict__ w_i, const float* __restrict__ b_i,
    const float* __restrict__ a_i, const int* __restrict__ idx)
{
    __shared__ float sray[D_DIM];
    __shared__ float sdec[8][64];

    const int tid = threadIdx.x;
    for (int i = tid; i < D_DIM; i += 256) sray[i] = ray[i];
    __syncthreads();

    const int warp = tid >> 5;
    const int lane = tid & 31;
    const int row  = blockIdx.x * 8 + warp;

    const float* xr = x + (size_t)row * D_DIM;
    float dot = 0.f, ss = 0.f, rss = 0.f;
#pragma unroll
    for (int j = 0; j < 4; j++) {
        float4 xv = reinterpret_cast<const float4*>(xr)[lane + 32 * j];
        float4 rv = reinterpret_cast<const float4*>(sray)[lane + 32 * j];
        dot += xv.x * rv.x + xv.y * rv.y + xv.z * rv.z + xv.w * rv.w;
        ss  += xv.x * xv.x + xv.y * xv.y + xv.z * xv.z + xv.w * xv.w;
        rss += rv.x * rv.x + rv.y * rv.y + rv.z * rv.z + rv.w * rv.w;
    }
#pragma unroll
    for (int o = 16; o > 0; o >>= 1) {
        dot += __shfl_xor_sync(0xffffffffu, dot, o);
        ss  += __shfl_xor_sync(0xffffffffu, ss,  o);
        rss += __shfl_xor_sync(0xffffffffu, rss, o);
    }
    float xn = fmaxf(sqrtf(ss),  1e-8f);
    float rn = fmaxf(sqrtf(rss), 1e-8f);
    float c  = dot / (xn * rn);
    c = fminf(fmaxf(c, -1.0f), 1.0f);
    const float angle = acosf(c) * 0.3183098861837907f;

    for (int n = lane; n < N_NODE; n += 32) {
        float nf = (0.5f + sigmoidf_(w_i[n])) * angle - sigmoidf_(b_i[n]);
        sdec[warp][n] = sigmoidf_(nf * (1.0f + a_i[n]));
    }
    __syncwarp();

    for (int leaf = lane; leaf < N_LEAF; leaf += 32) {
        float p = 1.0f;
#pragma unroll
        for (int t = 0; t < 6; t++) {
            int j = idx[leaf * 6 + t];
            float v = (j < N_NODE) ? sdec[warp][j] : (1.0f - sdec[warp][j - N_NODE]);
            p *= v;
        }
        g_dist[row * N_LEAF + leaf] = p;
    }
}

// ---------------------------------------------------------------------------
// Kernel 2: tf32 warp-mma GEMM with register-resident A fragments.
// CTA: 128m x 64n, 256 threads = 8 warps (4m x 2n), warp tile 32x32.
// k in 8 chunks of 64; per chunk, A fragments are held in registers across
// the 64-leaf inner loop (zero A smem reads per leaf). B double-buffered
// via cp.async. Per-leaf epilogue: O += d[m,l] * P.
// ---------------------------------------------------------------------------
// smem layout (floats): X [128][68] @0 (8704) | B 2x[64][68] @8704 (8704) |
//                       Dt [128][68] @17408 (8704)  -> 26112 floats = 104448 B
#define XF  0
#define BF  8704
#define DTF 17408
#define SMEM_BYTES (26112 * 4)

__device__ __forceinline__ void issue_b(uint32_t dstbase, int l, int kb, int n0, int tid) {
    const float* src = g_T + ((size_t)l * W_DIM + n0) * D_DIM + kb;
#pragma unroll
    for (int e = 0; e < 4; e++) {
        int id = tid + e * 256;
        int n = id >> 4, c = id & 15;
        uint32_t dst = dstbase + n * 272 + c * 16;
        CP_ASYNC16(dst, (const char*)(src + (size_t)n * D_DIM) + c * 16);
    }
}

__global__ void __launch_bounds__(256, 1) gemm_tf32_kernel(
    const float* __restrict__ x, float* __restrict__ out)
{
    extern __shared__ float sm[];
    const uint32_t sb = smem_u32(sm);
    const int tid  = threadIdx.x;
    const int wid  = tid >> 5;
    const int lane = tid & 31;
    const int wm   = wid & 3;
    const int wn   = wid >> 2;
    const int g    = lane >> 2;
    const int tg   = lane & 3;
    const int m0 = blockIdx.y * 128;
    const int n0 = blockIdx.x * 64;

    float* Dt = sm + DTF;

    // Load distribution tile [128 x 64], pitch 68
#pragma unroll
    for (int e = 0; e < 8; e++) {
        int id = tid + e * 256;
        int r = id >> 4, q = id & 15;
        float4 v = reinterpret_cast<const float4*>(g_dist + (size_t)(m0 + r) * N_LEAF)[q];
        *reinterpret_cast<float4*>(Dt + r * 68 + q * 4) = v;
    }

    float O[2][4][4];
#pragma unroll
    for (int i = 0; i < 2; i++)
#pragma unroll
        for (int j = 0; j < 4; j++)
#pragma unroll
            for (int r = 0; r < 4; r++) O[i][j][r] = 0.f;

    // Prologue: prefetch B(leaf 0, kc 0) into buffer 0
    issue_b(sb + BF * 4, 0, 0, n0, tid);
    CP_COMMIT();

    int p = 0;
    for (int kc = 0; kc < 8; kc++) {
        const int kb = kc * 64;

        // ---- build X tile [128m x 64k] tf32, pitch 68 ----
        const float* xp = x + (size_t)m0 * D_DIM + kb;
#pragma unroll
        for (int e = 0; e < 8; e++) {
            int id = tid + e * 256;            // 2048 float4 = 128 x 16
            int m = id >> 4, q = id & 15;
            float4 v = *reinterpret_cast<const float4*>(xp + (size_t)m * D_DIM + q * 4);
            uint4 u = make_uint4(to_tf32(v.x), to_tf32(v.y), to_tf32(v.z), to_tf32(v.w));
            *reinterpret_cast<uint4*>(sm + XF + m * 68 + q * 4) = u;
        }
        CP_WAIT0();            // current B buffer landed
        __syncthreads();       // X + Dt + B visible

        // ---- load A fragments into registers (held across the leaf loop) ----
        uint32_t A[8][2][4];
        const uint32_t* Xs = reinterpret_cast<const uint32_t*>(sm + XF);
#pragma unroll
        for (int ks = 0; ks < 8; ks++) {
#pragma unroll
            for (int i = 0; i < 2; i++) {
                int m = wm * 32 + i * 16 + g;
                int k = ks * 8 + tg;
                A[ks][i][0] = Xs[m * 68 + k];
                A[ks][i][1] = Xs[(m + 8) * 68 + k];
                A[ks][i][2] = Xs[m * 68 + k + 4];
                A[ks][i][3] = Xs[(m + 8) * 68 + k + 4];
            }
        }

        for (int l = 0; l < N_LEAF; l++) {
            // Prefetch next B tile into the other buffer (overlaps compute)
            if (l < 63)       issue_b(sb + BF * 4 + (p ^ 1) * 17408, l + 1, kb,      n0, tid);
            else if (kc < 7)  issue_b(sb + BF * 4 + (p ^ 1) * 17408, 0,     kb + 64, n0, tid);
            CP_COMMIT();

            const uint32_t* Bs = reinterpret_cast<const uint32_t*>(sm + BF + p * 4352);

            float P[2][4][4];
#pragma unroll
            for (int i = 0; i < 2; i++)
#pragma unroll
                for (int j = 0; j < 4; j++)
#pragma unroll
                    for (int r = 0; r < 4; r++) P[i][j][r] = 0.f;

#pragma unroll
            for (int ks = 0; ks < 8; ks++) {
                uint32_t b[4][2];
#pragma unroll
                for (int j = 0; j < 4; j++) {
                    int n = wn * 32 + j * 8 + g;
                    int k = ks * 8 + tg;
                    b[j][0] = Bs[n * 68 + k];
                    b[j][1] = Bs[n * 68 + k + 4];
                }
#pragma unroll
                for (int i = 0; i < 2; i++)
#pragma unroll
                    for (int j = 0; j < 4; j++)
                        mma_tf32(P[i][j], A[ks][i], b[j]);
            }

            // Epilogue: O += d[row, l] * P
#pragma unroll
            for (int i = 0; i < 2; i++) {
                int r0 = wm * 32 + i * 16 + g;
                float d0 = Dt[r0 * 68 + l];
                float d1 = Dt[(r0 + 8) * 68 + l];
#pragma unroll
                for (int j = 0; j < 4; j++) {
                    O[i][j][0] = fmaf(d0, P[i][j][0], O[i][j][0]);
                    O[i][j][1] = fmaf(d0, P[i][j][1], O[i][j][1]);
                    O[i][j][2] = fmaf(d1, P[i][j][2], O[i][j][2]);
                    O[i][j][3] = fmaf(d1, P[i][j][3], O[i][j][3]);
                }
            }

            CP_WAIT0();        // next buffer landed
            __syncthreads();   // safe to overwrite buffer p next iteration
            p ^= 1;
        }
    }

    // Write output fragments
#pragma unroll
    for (int i = 0; i < 2; i++) {
        int r0 = m0 + wm * 32 + i * 16 + g;
#pragma unroll
        for (int j = 0; j < 4; j++) {
            int col = n0 + wn * 32 + j * 8 + 2 * tg;
            float2 v0 = make_float2(O[i][j][0], O[i][j][1]);
            float2 v1 = make_float2(O[i][j][2], O[i][j][3]);
            *reinterpret_cast<float2*>(out + (size_t)r0 * W_DIM + col)       = v0;
            *reinterpret_cast<float2*>(out + (size_t)(r0 + 8) * W_DIM + col) = v1;
        }
    }
}

// ---------------------------------------------------------------------------
extern "C" void kernel_launch(void* const* d_in, const int* in_sizes, int n_in,
                              void* d_out, int out_size)
{
    const float* x   = (const float*)d_in[0];
    const float* ray = (const float*)d_in[1];
    const float* w_i = (const float*)d_in[2];
    const float* b_i = (const float*)d_in[3];
    const float* a_i = (const float*)d_in[4];
    const float* T   = (const float*)d_in[5];
    const int*   idx = (const int*)d_in[6];
    float* out = (float*)d_out;

    cudaFuncSetAttribute(gemm_tf32_kernel,
                         cudaFuncAttributeMaxDynamicSharedMemorySize, SMEM_BYTES);

    convert_kernel<<<dim3(8, 8, 64), 256>>>(T);
    dist_kernel<<<B_ROWS / 8, 256>>>(x, ray, w_i, b_i, a_i, idx);
    gemm_tf32_kernel<<<dim3(W_DIM / 64, B_ROWS / 128), 256, SMEM_BYTES>>>(x, out);
}

// round 6
// speedup vs baseline: 4.0223x; 1.1436x over previous
#include <cuda_runtime.h>
#include <cuda_bf16.h>
#include <math.h>
#include <stdint.h>

#define B_ROWS 2048
#define D_DIM  512
#define W_DIM  512
#define N_LEAF 64
#define N_NODE 63

// ---------------------------------------------------------------------------
// Device scratch (no cudaMalloc allowed)
// ---------------------------------------------------------------------------
__device__ float g_dist[B_ROWS * N_LEAF];
// Fragment-permuted, tf32-rounded T:
// g_Tp[l][nb][kc][ (wn*8+ks)*32 + lane ][8 words]
__device__ float g_Tp[(size_t)N_LEAF * D_DIM * W_DIM];

// ---------------------------------------------------------------------------
// Helpers
// ---------------------------------------------------------------------------
__device__ __forceinline__ uint32_t smem_u32(const void* p) {
    uint32_t a;
    asm("{ .reg .u64 t; cvta.to.shared.u64 t, %1; cvt.u32.u64 %0, t; }"
        : "=r"(a) : "l"(p));
    return a;
}

__device__ __forceinline__ uint32_t to_tf32(float f) {
    uint32_t u;
    asm("cvt.rna.tf32.f32 %0, %1;" : "=r"(u) : "f"(f));
    return u;
}

// Bank-conflict-killing swizzle: flip bit 4 when bit 7 is set.
// Applied IDENTICALLY on write (issue_b) and read (both granules).
__device__ __forceinline__ uint32_t swz(uint32_t a) {
    return a ^ (((a >> 7) & 1u) << 4);
}

__device__ __forceinline__ float sigmoidf_(float z) { return 1.0f / (1.0f + expf(-z)); }

__device__ __forceinline__ void mma_tf32(float c[4], const uint32_t a[4], const uint32_t b[2]) {
    asm volatile("mma.sync.aligned.m16n8k8.row.col.f32.tf32.tf32.f32 "
                 "{%0,%1,%2,%3}, {%4,%5,%6,%7}, {%8,%9}, {%0,%1,%2,%3};"
                 : "+f"(c[0]), "+f"(c[1]), "+f"(c[2]), "+f"(c[3])
                 : "r"(a[0]), "r"(a[1]), "r"(a[2]), "r"(a[3]), "r"(b[0]), "r"(b[1]));
}

#define CP_ASYNC16(dst, src) \
    asm volatile("cp.async.cg.shared.global [%0], [%1], 16;" :: "r"(dst), "l"(src))
#define CP_COMMIT() asm volatile("cp.async.commit_group;" ::: "memory")
#define CP_WAIT0()  asm volatile("cp.async.wait_group 0;" ::: "memory")

// ---------------------------------------------------------------------------
// Kernel 0: T [l][i][w] fp32 -> fragment-permuted tf32 g_Tp.
// One block per (kc, nb, l): 64k x 64n tile.
// ---------------------------------------------------------------------------
__global__ void __launch_bounds__(256) convert_kernel(const float* __restrict__ T) {
    __shared__ float tile[64][65];          // [k][n]
    const int tid = threadIdx.x;
    const int kc = blockIdx.x;
    const int nb = blockIdx.y;
    const int l  = blockIdx.z;

    const float* tp = T + ((size_t)l * D_DIM + kc * 64) * W_DIM + nb * 64;
#pragma unroll
    for (int e = 0; e < 16; e++) {
        int id = tid + e * 256;
        int k = id >> 6, n = id & 63;
        tile[k][n] = tp[(size_t)k * W_DIM + n];
    }
    __syncthreads();

    float* dst = g_Tp + (((size_t)l * 8 + nb) * 8 + kc) * 4096;
#pragma unroll
    for (int e = 0; e < 2; e++) {
        int r = tid + e * 256;               // 0..511 fragment rows
        int wn = r >> 8, ks = (r >> 5) & 7, ln = r & 31;
        int g = ln >> 2, tg = ln & 3;
        float w[8];
#pragma unroll
        for (int t = 0; t < 8; t++) {
            int j = t >> 1, h = t & 1;
            w[t] = __uint_as_float(to_tf32(tile[ks * 8 + tg + h * 4][wn * 32 + j * 8 + g]));
        }
        *reinterpret_cast<float4*>(dst + r * 8)     = make_float4(w[0], w[1], w[2], w[3]);
        *reinterpret_cast<float4*>(dst + r * 8 + 4) = make_float4(w[4], w[5], w[6], w[7]);
    }
}

// ---------------------------------------------------------------------------
// Kernel 1: angles -> decisions -> leaf distribution.  One warp per row.
// ---------------------------------------------------------------------------
__global__ void __launch_bounds__(256) dist_kernel(
    const float* __restrict__ x, const float* __restrict__ ray,
    const float* __restrict__ w_i, const float* __restrict__ b_i,
    const float* __restrict__ a_i, const int* __restrict__ idx)
{
    __shared__ float sray[D_DIM];
    __shared__ float sdec[8][64];

    const int tid = threadIdx.x;
    for (int i = tid; i < D_DIM; i += 256) sray[i] = ray[i];
    __syncthreads();

    const int warp = tid >> 5;
    const int lane = tid & 31;
    const int row  = blockIdx.x * 8 + warp;

    const float* xr = x + (size_t)row * D_DIM;
    float dot = 0.f, ss = 0.f, rss = 0.f;
#pragma unroll
    for (int j = 0; j < 4; j++) {
        float4 xv = reinterpret_cast<const float4*>(xr)[lane + 32 * j];
        float4 rv = reinterpret_cast<const float4*>(sray)[lane + 32 * j];
        dot += xv.x * rv.x + xv.y * rv.y + xv.z * rv.z + xv.w * rv.w;
        ss  += xv.x * xv.x + xv.y * xv.y + xv.z * xv.z + xv.w * xv.w;
        rss += rv.x * rv.x + rv.y * rv.y + rv.z * rv.z + rv.w * rv.w;
    }
#pragma unroll
    for (int o = 16; o > 0; o >>= 1) {
        dot += __shfl_xor_sync(0xffffffffu, dot, o);
        ss  += __shfl_xor_sync(0xffffffffu, ss,  o);
        rss += __shfl_xor_sync(0xffffffffu, rss, o);
    }
    float xn = fmaxf(sqrtf(ss),  1e-8f);
    float rn = fmaxf(sqrtf(rss), 1e-8f);
    float c  = dot / (xn * rn);
    c = fminf(fmaxf(c, -1.0f), 1.0f);
    const float angle = acosf(c) * 0.3183098861837907f;

    for (int n = lane; n < N_NODE; n += 32) {
        float nf = (0.5f + sigmoidf_(w_i[n])) * angle - sigmoidf_(b_i[n]);
        sdec[warp][n] = sigmoidf_(nf * (1.0f + a_i[n]));
    }
    __syncwarp();

    for (int leaf = lane; leaf < N_LEAF; leaf += 32) {
        float p = 1.0f;
#pragma unroll
        for (int t = 0; t < 6; t++) {
            int j = idx[leaf * 6 + t];
            float v = (j < N_NODE) ? sdec[warp][j] : (1.0f - sdec[warp][j - N_NODE]);
            p *= v;
        }
        g_dist[row * N_LEAF + leaf] = p;
    }
}

// ---------------------------------------------------------------------------
// Kernel 2: tf32 warp-mma GEMM, register-resident A, fragment-order B.
// CTA: 128m x 64n, 256 threads = 8 warps (4m x 2n), warp tile 32x32.
// Per leaf-iter each lane loads its B frags with 2x LDS.128 per ks.
// ---------------------------------------------------------------------------
// smem floats: X [128][68] @0 (8704) | B 2x4096 @8704 | Dt [128][68] @16896
#define XF  0
#define BF  8704
#define DTF 16896
#define SMEM_BYTES (25600 * 4)

__device__ __forceinline__ void issue_b(uint32_t dstbase, int l, int nb, int kc, int tid) {
    const char* src = (const char*)(g_Tp + (((size_t)l * 8 + nb) * 8 + kc) * 4096);
#pragma unroll
    for (int e = 0; e < 4; e++) {
        int id = tid + e * 256;                 // 0..1023 16B granules
        uint32_t off = (uint32_t)id * 16;
        CP_ASYNC16(dstbase + swz(off), src + off);
    }
}

__global__ void __launch_bounds__(256, 1) gemm_tf32_kernel(
    const float* __restrict__ x, float* __restrict__ out)
{
    extern __shared__ float sm[];
    const uint32_t sb = smem_u32(sm);
    const int tid  = threadIdx.x;
    const int wid  = tid >> 5;
    const int lane = tid & 31;
    const int wm   = wid & 3;
    const int wn   = wid >> 2;
    const int g    = lane >> 2;
    const int tg   = lane & 3;
    const int m0 = blockIdx.y * 128;
    const int nb = blockIdx.x;
    const int n0 = nb * 64;

    float* Dt = sm + DTF;
    // Both granule addresses go through the SAME swizzle as the writer.
    const uint32_t lane_sw0 = swz((uint32_t)lane * 32);
    const uint32_t lane_sw1 = swz((uint32_t)lane * 32 + 16);

    // Load distribution tile [128 x 64], pitch 68
#pragma unroll
    for (int e = 0; e < 8; e++) {
        int id = tid + e * 256;
        int r = id >> 4, q = id & 15;
        float4 v = reinterpret_cast<const float4*>(g_dist + (size_t)(m0 + r) * N_LEAF)[q];
        *reinterpret_cast<float4*>(Dt + r * 68 + q * 4) = v;
    }

    float O[2][4][4];
#pragma unroll
    for (int i = 0; i < 2; i++)
#pragma unroll
        for (int j = 0; j < 4; j++)
#pragma unroll
            for (int r = 0; r < 4; r++) O[i][j][r] = 0.f;

    // Prologue: prefetch B(leaf 0, kc 0) into buffer 0
    issue_b(sb + BF * 4, 0, nb, 0, tid);
    CP_COMMIT();

    int p = 0;
    for (int kc = 0; kc < 8; kc++) {
        const int kb = kc * 64;

        // ---- build X tile [128m x 64k] tf32, pitch 68 ----
        const float* xp = x + (size_t)m0 * D_DIM + kb;
#pragma unroll
        for (int e = 0; e < 8; e++) {
            int id = tid + e * 256;
            int m = id >> 4, q = id & 15;
            float4 v = *reinterpret_cast<const float4*>(xp + (size_t)m * D_DIM + q * 4);
            uint4 u = make_uint4(to_tf32(v.x), to_tf32(v.y), to_tf32(v.z), to_tf32(v.w));
            *reinterpret_cast<uint4*>(sm + XF + m * 68 + q * 4) = u;
        }
        CP_WAIT0();
        __syncthreads();

        // ---- A fragments into registers (held across the leaf loop) ----
        uint32_t A[8][2][4];
        const uint32_t* Xs = reinterpret_cast<const uint32_t*>(sm + XF);
#pragma unroll
        for (int ks = 0; ks < 8; ks++) {
#pragma unroll
            for (int i = 0; i < 2; i++) {
                int m = wm * 32 + i * 16 + g;
                int k = ks * 8 + tg;
                A[ks][i][0] = Xs[m * 68 + k];
                A[ks][i][1] = Xs[(m + 8) * 68 + k];
                A[ks][i][2] = Xs[m * 68 + k + 4];
                A[ks][i][3] = Xs[(m + 8) * 68 + k + 4];
            }
        }

        for (int l = 0; l < N_LEAF; l++) {
            if (l < 63)       issue_b(sb + BF * 4 + (p ^ 1) * 16384, l + 1, nb, kc,     tid);
            else if (kc < 7)  issue_b(sb + BF * 4 + (p ^ 1) * 16384, 0,     nb, kc + 1, tid);
            CP_COMMIT();

            const char* Bb = (const char*)(sm + BF + p * 4096) + (wn * 8) * 1024;

            float P[2][4][4];
#pragma unroll
            for (int i = 0; i < 2; i++)
#pragma unroll
                for (int j = 0; j < 4; j++)
#pragma unroll
                    for (int r = 0; r < 4; r++) P[i][j][r] = 0.f;

            uint4 c0 = *reinterpret_cast<const uint4*>(Bb + lane_sw0);
            uint4 c1 = *reinterpret_cast<const uint4*>(Bb + lane_sw1);
#pragma unroll
            for (int ks = 0; ks < 8; ks++) {
                uint4 n0_, n1_;
                if (ks < 7) {
                    n0_ = *reinterpret_cast<const uint4*>(Bb + (ks + 1) * 1024 + lane_sw0);
                    n1_ = *reinterpret_cast<const uint4*>(Bb + (ks + 1) * 1024 + lane_sw1);
                }
                uint32_t b[4][2];
                b[0][0] = c0.x; b[0][1] = c0.y;
                b[1][0] = c0.z; b[1][1] = c0.w;
                b[2][0] = c1.x; b[2][1] = c1.y;
                b[3][0] = c1.z; b[3][1] = c1.w;
#pragma unroll
                for (int i = 0; i < 2; i++)
#pragma unroll
                    for (int j = 0; j < 4; j++)
                        mma_tf32(P[i][j], A[ks][i], b[j]);
                c0 = n0_; c1 = n1_;
            }

            // Epilogue: O += d[row, l] * P
#pragma unroll
            for (int i = 0; i < 2; i++) {
                int r0 = wm * 32 + i * 16 + g;
                float d0 = Dt[r0 * 68 + l];
                float d1 = Dt[(r0 + 8) * 68 + l];
#pragma unroll
                for (int j = 0; j < 4; j++) {
                    O[i][j][0] = fmaf(d0, P[i][j][0], O[i][j][0]);
                    O[i][j][1] = fmaf(d0, P[i][j][1], O[i][j][1]);
                    O[i][j][2] = fmaf(d1, P[i][j][2], O[i][j][2]);
                    O[i][j][3] = fmaf(d1, P[i][j][3], O[i][j][3]);
                }
            }

            CP_WAIT0();
            __syncthreads();
            p ^= 1;
        }
    }

    // Write output fragments
#pragma unroll
    for (int i = 0; i < 2; i++) {
        int r0 = m0 + wm * 32 + i * 16 + g;
#pragma unroll
        for (int j = 0; j < 4; j++) {
            int col = n0 + wn * 32 + j * 8 + 2 * tg;
            float2 v0 = make_float2(O[i][j][0], O[i][j][1]);
            float2 v1 = make_float2(O[i][j][2], O[i][j][3]);
            *reinterpret_cast<float2*>(out + (size_t)r0 * W_DIM + col)       = v0;
            *reinterpret_cast<float2*>(out + (size_t)(r0 + 8) * W_DIM + col) = v1;
        }
    }
}

// ---------------------------------------------------------------------------
extern "C" void kernel_launch(void* const* d_in, const int* in_sizes, int n_in,
                              void* d_out, int out_size)
{
    const float* x   = (const float*)d_in[0];
    const float* ray = (const float*)d_in[1];
    const float* w_i = (const float*)d_in[2];
    const float* b_i = (const float*)d_in[3];
    const float* a_i = (const float*)d_in[4];
    const float* T   = (const float*)d_in[5];
    const int*   idx = (const int*)d_in[6];
    float* out = (float*)d_out;

    cudaFuncSetAttribute(gemm_tf32_kernel,
                         cudaFuncAttributeMaxDynamicSharedMemorySize, SMEM_BYTES);

    convert_kernel<<<dim3(8, 8, 64), 256>>>(T);
    dist_kernel<<<B_ROWS / 8, 256>>>(x, ray, w_i, b_i, a_i, idx);
    gemm_tf32_kernel<<<dim3(W_DIM / 64, B_ROWS / 128), 256, SMEM_BYTES>>>(x, out);
}

// round 7
// speedup vs baseline: 5.2743x; 1.3113x over previous
#include <cuda_runtime.h>
#include <cuda_fp16.h>
#include <math.h>
#include <stdint.h>

#define B_ROWS 2048
#define D_DIM  512
#define W_DIM  512
#define N_LEAF 64
#define N_NODE 63

// ---------------------------------------------------------------------------
// Device scratch (no cudaMalloc allowed)
// ---------------------------------------------------------------------------
__device__ float g_dist[B_ROWS * N_LEAF];
// Fragment-permuted fp16 T: per (l, nb, kc) an 8KB tile of 256 fragment rows
// row r = (wn*4 + ks)*32 + lane, 8 half2 words (32 B) each.
__device__ __half g_Tp[(size_t)N_LEAF * 8 * 8 * 4096];

// ---------------------------------------------------------------------------
// Helpers
// ---------------------------------------------------------------------------
__device__ __forceinline__ uint32_t smem_u32(const void* p) {
    uint32_t a;
    asm("{ .reg .u64 t; cvta.to.shared.u64 t, %1; cvt.u32.u64 %0, t; }"
        : "=r"(a) : "l"(p));
    return a;
}

// Bank-conflict-killing swizzle: flip bit 4 when bit 7 is set.
// Applied IDENTICALLY on cp.async write and on both LDS.128 read granules.
__device__ __forceinline__ uint32_t swz(uint32_t a) {
    return a ^ (((a >> 7) & 1u) << 4);
}

__device__ __forceinline__ float sigmoidf_(float z) { return 1.0f / (1.0f + expf(-z)); }

__device__ __forceinline__ void mma_f16(float c[4], const uint32_t a[4], const uint32_t b[2]) {
    asm volatile("mma.sync.aligned.m16n8k16.row.col.f32.f16.f16.f32 "
                 "{%0,%1,%2,%3}, {%4,%5,%6,%7}, {%8,%9}, {%0,%1,%2,%3};"
                 : "+f"(c[0]), "+f"(c[1]), "+f"(c[2]), "+f"(c[3])
                 : "r"(a[0]), "r"(a[1]), "r"(a[2]), "r"(a[3]), "r"(b[0]), "r"(b[1]));
}

__device__ __forceinline__ uint32_t pack_h2(float a, float b) {
    __half2 t = __floats2half2_rn(a, b);
    return *reinterpret_cast<uint32_t*>(&t);
}

#define CP_ASYNC16(dst, src) \
    asm volatile("cp.async.cg.shared.global [%0], [%1], 16;" :: "r"(dst), "l"(src))
#define CP_COMMIT() asm volatile("cp.async.commit_group;" ::: "memory")
#define CP_WAIT0()  asm volatile("cp.async.wait_group 0;" ::: "memory")

// ---------------------------------------------------------------------------
// Kernel 0: T [l][k][n] fp32 -> fragment-permuted fp16 g_Tp.
// One block per (kc, nb, l): 64k x 64n tile -> 256 fragment rows x 32 B.
// ---------------------------------------------------------------------------
__global__ void __launch_bounds__(256) convert_kernel(const float* __restrict__ T) {
    __shared__ float tile[64][65];          // [k][n]
    const int tid = threadIdx.x;
    const int kc = blockIdx.x;
    const int nb = blockIdx.y;
    const int l  = blockIdx.z;

    const float* tp = T + ((size_t)l * D_DIM + kc * 64) * W_DIM + nb * 64;
#pragma unroll
    for (int e = 0; e < 16; e++) {
        int id = tid + e * 256;
        int k = id >> 6, n = id & 63;
        tile[k][n] = tp[(size_t)k * W_DIM + n];
    }
    __syncthreads();

    __half* dst = g_Tp + (((size_t)l * 8 + nb) * 8 + kc) * 4096;
    // one fragment row per thread: r = tid (0..255)
    const int r  = tid;
    const int wn = r >> 7, ks = (r >> 5) & 3, ln = r & 31;
    const int g = ln >> 2, tg = ln & 3;
    uint32_t w[8];
#pragma unroll
    for (int j = 0; j < 4; j++) {
        int n  = wn * 32 + j * 8 + g;
        int k0 = ks * 16 + 2 * tg;
        w[2 * j]     = pack_h2(tile[k0][n],     tile[k0 + 1][n]);
        w[2 * j + 1] = pack_h2(tile[k0 + 8][n], tile[k0 + 9][n]);
    }
    uint32_t* d = reinterpret_cast<uint32_t*>(dst + (size_t)r * 16);
    *reinterpret_cast<uint4*>(d)     = make_uint4(w[0], w[1], w[2], w[3]);
    *reinterpret_cast<uint4*>(d + 4) = make_uint4(w[4], w[5], w[6], w[7]);
}

// ---------------------------------------------------------------------------
// Kernel 1: angles -> decisions -> leaf distribution.  One warp per row.
// ---------------------------------------------------------------------------
__global__ void __launch_bounds__(256) dist_kernel(
    const float* __restrict__ x, const float* __restrict__ ray,
    const float* __restrict__ w_i, const float* __restrict__ b_i,
    const float* __restrict__ a_i, const int* __restrict__ idx)
{
    __shared__ float sray[D_DIM];
    __shared__ float sdec[8][64];

    const int tid = threadIdx.x;
    for (int i = tid; i < D_DIM; i += 256) sray[i] = ray[i];
    __syncthreads();

    const int warp = tid >> 5;
    const int lane = tid & 31;
    const int row  = blockIdx.x * 8 + warp;

    const float* xr = x + (size_t)row * D_DIM;
    float dot = 0.f, ss = 0.f, rss = 0.f;
#pragma unroll
    for (int j = 0; j < 4; j++) {
        float4 xv = reinterpret_cast<const float4*>(xr)[lane + 32 * j];
        float4 rv = reinterpret_cast<const float4*>(sray)[lane + 32 * j];
        dot += xv.x * rv.x + xv.y * rv.y + xv.z * rv.z + xv.w * rv.w;
        ss  += xv.x * xv.x + xv.y * xv.y + xv.z * xv.z + xv.w * xv.w;
        rss += rv.x * rv.x + rv.y * rv.y + rv.z * rv.z + rv.w * rv.w;
    }
#pragma unroll
    for (int o = 16; o > 0; o >>= 1) {
        dot += __shfl_xor_sync(0xffffffffu, dot, o);
        ss  += __shfl_xor_sync(0xffffffffu, ss,  o);
        rss += __shfl_xor_sync(0xffffffffu, rss, o);
    }
    float xn = fmaxf(sqrtf(ss),  1e-8f);
    float rn = fmaxf(sqrtf(rss), 1e-8f);
    float c  = dot / (xn * rn);
    c = fminf(fmaxf(c, -1.0f), 1.0f);
    const float angle = acosf(c) * 0.3183098861837907f;

    for (int n = lane; n < N_NODE; n += 32) {
        float nf = (0.5f + sigmoidf_(w_i[n])) * angle - sigmoidf_(b_i[n]);
        sdec[warp][n] = sigmoidf_(nf * (1.0f + a_i[n]));
    }
    __syncwarp();

    for (int leaf = lane; leaf < N_LEAF; leaf += 32) {
        float p = 1.0f;
#pragma unroll
        for (int t = 0; t < 6; t++) {
            int j = idx[leaf * 6 + t];
            float v = (j < N_NODE) ? sdec[warp][j] : (1.0f - sdec[warp][j - N_NODE]);
            p *= v;
        }
        g_dist[row * N_LEAF + leaf] = p;
    }
}

// ---------------------------------------------------------------------------
// Kernel 2: fp16 warp-mma GEMM, register-resident A, fragment-order B.
// CTA: 128m x 64n, 256 threads = 8 warps (4m x 2n), warp tile 32x32.
// kc chunks of 64 (4 x k16 steps). Per leaf-iter: 8 LDS.128 + 32 HMMA/warp.
// ---------------------------------------------------------------------------
// smem bytes: X half2-words [128][36] @0 (18432) | B 2x8192 @18432 | Dt @34816
#define XWOFF  0
#define BOFF   18432
#define DTOFF  34816
#define SMEM_BYTES (34816 + 34816)

__device__ __forceinline__ void issue_b(uint32_t dstbase, int l, int nb, int kc, int tid) {
    const char* src = (const char*)(g_Tp + (((size_t)l * 8 + nb) * 8 + kc) * 4096);
#pragma unroll
    for (int e = 0; e < 2; e++) {
        int id = tid + e * 256;                 // 0..511 16B granules
        uint32_t off = (uint32_t)id * 16;
        CP_ASYNC16(dstbase + swz(off), src + off);
    }
}

__global__ void __launch_bounds__(256, 1) gemm_f16_kernel(
    const float* __restrict__ x, float* __restrict__ out)
{
    extern __shared__ char sm[];
    const uint32_t sb = smem_u32(sm);
    const int tid  = threadIdx.x;
    const int wid  = tid >> 5;
    const int lane = tid & 31;
    const int wm   = wid & 3;
    const int wn   = wid >> 2;
    const int g    = lane >> 2;
    const int tg   = lane & 3;
    const int m0 = blockIdx.y * 128;
    const int nb = blockIdx.x;
    const int n0 = nb * 64;

    uint32_t* XW = reinterpret_cast<uint32_t*>(sm + XWOFF);  // half2 words, pitch 36
    float*    Dt = reinterpret_cast<float*>(sm + DTOFF);     // pitch 68
    const uint32_t lane_sw0 = swz((uint32_t)lane * 32);
    const uint32_t lane_sw1 = swz((uint32_t)lane * 32 + 16);

    // Load distribution tile [128 x 64], pitch 68
#pragma unroll
    for (int e = 0; e < 8; e++) {
        int id = tid + e * 256;
        int r = id >> 4, q = id & 15;
        float4 v = reinterpret_cast<const float4*>(g_dist + (size_t)(m0 + r) * N_LEAF)[q];
        *reinterpret_cast<float4*>(Dt + r * 68 + q * 4) = v;
    }

    float O[2][4][4];
#pragma unroll
    for (int i = 0; i < 2; i++)
#pragma unroll
        for (int j = 0; j < 4; j++)
#pragma unroll
            for (int r = 0; r < 4; r++) O[i][j][r] = 0.f;

    // Prologue: prefetch B(leaf 0, kc 0) into buffer 0
    issue_b(sb + BOFF, 0, nb, 0, tid);
    CP_COMMIT();

    int p = 0;
    for (int kc = 0; kc < 8; kc++) {
        // ---- build X tile [128m x 64k] fp16 (half2 words, pitch 36) ----
        const float* xp = x + (size_t)m0 * D_DIM + kc * 64;
#pragma unroll
        for (int e = 0; e < 8; e++) {
            int id = tid + e * 256;            // 0..2047 float4s (128 rows x 16)
            int m = id >> 4, q = id & 15;
            float4 v = *reinterpret_cast<const float4*>(xp + (size_t)m * D_DIM + q * 4);
            uint2 u = make_uint2(pack_h2(v.x, v.y), pack_h2(v.z, v.w));
            *reinterpret_cast<uint2*>(XW + m * 36 + q * 2) = u;
        }
        CP_WAIT0();
        __syncthreads();

        // ---- A fragments into registers (held across the leaf loop) ----
        uint32_t A[4][2][4];
#pragma unroll
        for (int ks = 0; ks < 4; ks++) {
#pragma unroll
            for (int i = 0; i < 2; i++) {
                int m = wm * 32 + i * 16 + g;
                int k = ks * 8 + tg;           // half2-word index within row
                A[ks][i][0] = XW[m * 36 + k];
                A[ks][i][1] = XW[(m + 8) * 36 + k];
                A[ks][i][2] = XW[m * 36 + k + 4];
                A[ks][i][3] = XW[(m + 8) * 36 + k + 4];
            }
        }

        for (int l = 0; l < N_LEAF; l++) {
            if (l < 63)       issue_b(sb + BOFF + (p ^ 1) * 8192, l + 1, nb, kc,     tid);
            else if (kc < 7)  issue_b(sb + BOFF + (p ^ 1) * 8192, 0,     nb, kc + 1, tid);
            CP_COMMIT();

            const char* Bb = sm + BOFF + p * 8192 + wn * 4096;

            float P[2][4][4];
#pragma unroll
            for (int i = 0; i < 2; i++)
#pragma unroll
                for (int j = 0; j < 4; j++)
#pragma unroll
                    for (int r = 0; r < 4; r++) P[i][j][r] = 0.f;

            uint4 c0 = *reinterpret_cast<const uint4*>(Bb + lane_sw0);
            uint4 c1 = *reinterpret_cast<const uint4*>(Bb + lane_sw1);
#pragma unroll
            for (int ks = 0; ks < 4; ks++) {
                uint4 n0_, n1_;
                if (ks < 3) {
                    n0_ = *reinterpret_cast<const uint4*>(Bb + (ks + 1) * 1024 + lane_sw0);
                    n1_ = *reinterpret_cast<const uint4*>(Bb + (ks + 1) * 1024 + lane_sw1);
                }
                uint32_t b[4][2];
                b[0][0] = c0.x; b[0][1] = c0.y;
                b[1][0] = c0.z; b[1][1] = c0.w;
                b[2][0] = c1.x; b[2][1] = c1.y;
                b[3][0] = c1.z; b[3][1] = c1.w;
#pragma unroll
                for (int i = 0; i < 2; i++)
#pragma unroll
                    for (int j = 0; j < 4; j++)
                        mma_f16(P[i][j], A[ks][i], b[j]);
                c0 = n0_; c1 = n1_;
            }

            // Epilogue: O += d[row, l] * P
#pragma unroll
            for (int i = 0; i < 2; i++) {
                int r0 = wm * 32 + i * 16 + g;
                float d0 = Dt[r0 * 68 + l];
                float d1 = Dt[(r0 + 8) * 68 + l];
#pragma unroll
                for (int j = 0; j < 4; j++) {
                    O[i][j][0] = fmaf(d0, P[i][j][0], O[i][j][0]);
                    O[i][j][1] = fmaf(d0, P[i][j][1], O[i][j][1]);
                    O[i][j][2] = fmaf(d1, P[i][j][2], O[i][j][2]);
                    O[i][j][3] = fmaf(d1, P[i][j][3], O[i][j][3]);
                }
            }

            CP_WAIT0();
            __syncthreads();
            p ^= 1;
        }
    }

    // Write output fragments
#pragma unroll
    for (int i = 0; i < 2; i++) {
        int r0 = m0 + wm * 32 + i * 16 + g;
#pragma unroll
        for (int j = 0; j < 4; j++) {
            int col = n0 + wn * 32 + j * 8 + 2 * tg;
            float2 v0 = make_float2(O[i][j][0], O[i][j][1]);
            float2 v1 = make_float2(O[i][j][2], O[i][j][3]);
            *reinterpret_cast<float2*>(out + (size_t)r0 * W_DIM + col)       = v0;
            *reinterpret_cast<float2*>(out + (size_t)(r0 + 8) * W_DIM + col) = v1;
        }
    }
}

// ---------------------------------------------------------------------------
extern "C" void kernel_launch(void* const* d_in, const int* in_sizes, int n_in,
                              void* d_out, int out_size)
{
    const float* x   = (const float*)d_in[0];
    const float* ray = (const float*)d_in[1];
    const float* w_i = (const float*)d_in[2];
    const float* b_i = (const float*)d_in[3];
    const float* a_i = (const float*)d_in[4];
    const float* T   = (const float*)d_in[5];
    const int*   idx = (const int*)d_in[6];
    float* out = (float*)d_out;

    cudaFuncSetAttribute(gemm_f16_kernel,
                         cudaFuncAttributeMaxDynamicSharedMemorySize, SMEM_BYTES);

    convert_kernel<<<dim3(8, 8, 64), 256>>>(T);
    dist_kernel<<<B_ROWS / 8, 256>>>(x, ray, w_i, b_i, a_i, idx);
    gemm_f16_kernel<<<dim3(W_DIM / 64, B_ROWS / 128), 256, SMEM_BYTES>>>(x, out);
}

// round 8
// speedup vs baseline: 6.7847x; 1.2864x over previous
#include <cuda_runtime.h>
#include <cuda_fp16.h>
#include <math.h>
#include <stdint.h>

#define B_ROWS 2048
#define D_DIM  512
#define W_DIM  512
#define N_LEAF 64
#define N_NODE 63

// ---------------------------------------------------------------------------
// Device scratch (no cudaMalloc allowed)
// ---------------------------------------------------------------------------
__device__ float g_dist[B_ROWS * N_LEAF];
// Fragment-permuted fp16 T: per (l, nb, kc) an 8KB tile of 256 fragment rows
// row r = (wn*4 + ks)*32 + lane, 8 half2 words (32 B) each.
__device__ __half g_Tp[(size_t)N_LEAF * 8 * 8 * 4096];

// ---------------------------------------------------------------------------
// Helpers
// ---------------------------------------------------------------------------
__device__ __forceinline__ uint32_t smem_u32(const void* p) {
    uint32_t a;
    asm("{ .reg .u64 t; cvta.to.shared.u64 t, %1; cvt.u32.u64 %0, t; }"
        : "=r"(a) : "l"(p));
    return a;
}

// Bank-conflict-killing swizzle: flip bit 4 when bit 7 is set.
// Applied IDENTICALLY on cp.async write and on both LDS.128 read granules.
__device__ __forceinline__ uint32_t swz(uint32_t a) {
    return a ^ (((a >> 7) & 1u) << 4);
}

__device__ __forceinline__ float sigmoidf_(float z) { return 1.0f / (1.0f + expf(-z)); }

__device__ __forceinline__ void mma_f16(float c[4], const uint32_t a[4], const uint32_t b[2]) {
    asm volatile("mma.sync.aligned.m16n8k16.row.col.f32.f16.f16.f32 "
                 "{%0,%1,%2,%3}, {%4,%5,%6,%7}, {%8,%9}, {%0,%1,%2,%3};"
                 : "+f"(c[0]), "+f"(c[1]), "+f"(c[2]), "+f"(c[3])
                 : "r"(a[0]), "r"(a[1]), "r"(a[2]), "r"(a[3]), "r"(b[0]), "r"(b[1]));
}

__device__ __forceinline__ uint32_t pack_h2(float a, float b) {
    __half2 t = __floats2half2_rn(a, b);
    return *reinterpret_cast<uint32_t*>(&t);
}

#define CP_ASYNC16(dst, src) \
    asm volatile("cp.async.cg.shared.global [%0], [%1], 16;" :: "r"(dst), "l"(src))
#define CP_COMMIT() asm volatile("cp.async.commit_group;" ::: "memory")
#define CP_WAIT1()  asm volatile("cp.async.wait_group 1;" ::: "memory")

// ---------------------------------------------------------------------------
// Kernel 0: T [l][k][n] fp32 -> fragment-permuted fp16 g_Tp.
// One block per (kc, nb, l): 64k x 64n tile -> 256 fragment rows x 32 B.
// ---------------------------------------------------------------------------
__global__ void __launch_bounds__(256) convert_kernel(const float* __restrict__ T) {
    __shared__ float tile[64][65];          // [k][n]
    const int tid = threadIdx.x;
    const int kc = blockIdx.x;
    const int nb = blockIdx.y;
    const int l  = blockIdx.z;

    const float* tp = T + ((size_t)l * D_DIM + kc * 64) * W_DIM + nb * 64;
#pragma unroll
    for (int e = 0; e < 16; e++) {
        int id = tid + e * 256;
        int k = id >> 6, n = id & 63;
        tile[k][n] = tp[(size_t)k * W_DIM + n];
    }
    __syncthreads();

    __half* dst = g_Tp + (((size_t)l * 8 + nb) * 8 + kc) * 4096;
    const int r  = tid;
    const int wn = r >> 7, ks = (r >> 5) & 3, ln = r & 31;
    const int g = ln >> 2, tg = ln & 3;
    uint32_t w[8];
#pragma unroll
    for (int j = 0; j < 4; j++) {
        int n  = wn * 32 + j * 8 + g;
        int k0 = ks * 16 + 2 * tg;
        w[2 * j]     = pack_h2(tile[k0][n],     tile[k0 + 1][n]);
        w[2 * j + 1] = pack_h2(tile[k0 + 8][n], tile[k0 + 9][n]);
    }
    uint32_t* d = reinterpret_cast<uint32_t*>(dst + (size_t)r * 16);
    *reinterpret_cast<uint4*>(d)     = make_uint4(w[0], w[1], w[2], w[3]);
    *reinterpret_cast<uint4*>(d + 4) = make_uint4(w[4], w[5], w[6], w[7]);
}

// ---------------------------------------------------------------------------
// Kernel 1: angles -> decisions -> leaf distribution.  One warp per row.
// ---------------------------------------------------------------------------
__global__ void __launch_bounds__(256) dist_kernel(
    const float* __restrict__ x, const float* __restrict__ ray,
    const float* __restrict__ w_i, const float* __restrict__ b_i,
    const float* __restrict__ a_i, const int* __restrict__ idx)
{
    __shared__ float sray[D_DIM];
    __shared__ float sdec[8][64];

    const int tid = threadIdx.x;
    for (int i = tid; i < D_DIM; i += 256) sray[i] = ray[i];
    __syncthreads();

    const int warp = tid >> 5;
    const int lane = tid & 31;
    const int row  = blockIdx.x * 8 + warp;

    const float* xr = x + (size_t)row * D_DIM;
    float dot = 0.f, ss = 0.f, rss = 0.f;
#pragma unroll
    for (int j = 0; j < 4; j++) {
        float4 xv = reinterpret_cast<const float4*>(xr)[lane + 32 * j];
        float4 rv = reinterpret_cast<const float4*>(sray)[lane + 32 * j];
        dot += xv.x * rv.x + xv.y * rv.y + xv.z * rv.z + xv.w * rv.w;
        ss  += xv.x * xv.x + xv.y * xv.y + xv.z * xv.z + xv.w * xv.w;
        rss += rv.x * rv.x + rv.y * rv.y + rv.z * rv.z + rv.w * rv.w;
    }
#pragma unroll
    for (int o = 16; o > 0; o >>= 1) {
        dot += __shfl_xor_sync(0xffffffffu, dot, o);
        ss  += __shfl_xor_sync(0xffffffffu, ss,  o);
        rss += __shfl_xor_sync(0xffffffffu, rss, o);
    }
    float xn = fmaxf(sqrtf(ss),  1e-8f);
    float rn = fmaxf(sqrtf(rss), 1e-8f);
    float c  = dot / (xn * rn);
    c = fminf(fmaxf(c, -1.0f), 1.0f);
    const float angle = acosf(c) * 0.3183098861837907f;

    for (int n = lane; n < N_NODE; n += 32) {
        float nf = (0.5f + sigmoidf_(w_i[n])) * angle - sigmoidf_(b_i[n]);
        sdec[warp][n] = sigmoidf_(nf * (1.0f + a_i[n]));
    }
    __syncwarp();

    for (int leaf = lane; leaf < N_LEAF; leaf += 32) {
        float p = 1.0f;
#pragma unroll
        for (int t = 0; t < 6; t++) {
            int j = idx[leaf * 6 + t];
            float v = (j < N_NODE) ? sdec[warp][j] : (1.0f - sdec[warp][j - N_NODE]);
            p *= v;
        }
        g_dist[row * N_LEAF + leaf] = p;
    }
}

// ---------------------------------------------------------------------------
// Kernel 2: fp16 warp-mma GEMM, 2 CTAs/SM, 3-stage cp.async pipeline.
// CTA: 64m x 64n, 128 threads = 4 warps (2m x 2n), warp tile 32x32.
// Flattened it = kc*64 + l over 512 B tiles; X rebuilt at l==0.
// ---------------------------------------------------------------------------
// smem bytes: X half2-words [64][36] @0 (9216) | B 3x8192 @9216 | Dt @33792
#define XWOFF  0
#define BOFF   9216
#define DTOFF  33792
#define SMEM_BYTES (33792 + 17408)

__device__ __forceinline__ void issue_b(uint32_t dstbase, int it, int nb, int tid) {
    const int kc = it >> 6, l = it & 63;
    const char* src = (const char*)(g_Tp + (((size_t)l * 8 + nb) * 8 + kc) * 4096);
#pragma unroll
    for (int e = 0; e < 4; e++) {
        int id = tid + e * 128;                 // 0..511 16B granules
        uint32_t off = (uint32_t)id * 16;
        CP_ASYNC16(dstbase + swz(off), src + off);
    }
}

__global__ void __launch_bounds__(128, 2) gemm_f16_kernel(
    const float* __restrict__ x, float* __restrict__ out)
{
    extern __shared__ char sm[];
    const uint32_t sb = smem_u32(sm);
    const int tid  = threadIdx.x;
    const int wid  = tid >> 5;
    const int lane = tid & 31;
    const int wm   = wid & 1;       // 2 m-warps
    const int wn   = wid >> 1;      // 2 n-warps
    const int g    = lane >> 2;
    const int tg   = lane & 3;
    const int m0 = blockIdx.y * 64;
    const int nb = blockIdx.x;
    const int n0 = nb * 64;

    uint32_t* XW = reinterpret_cast<uint32_t*>(sm + XWOFF);  // half2 words, pitch 36
    float*    Dt = reinterpret_cast<float*>(sm + DTOFF);     // pitch 68
    const uint32_t lane_sw0 = swz((uint32_t)lane * 32);
    const uint32_t lane_sw1 = swz((uint32_t)lane * 32 + 16);

    // Load distribution tile [64 x 64], pitch 68
#pragma unroll
    for (int e = 0; e < 8; e++) {
        int id = tid + e * 128;
        int r = id >> 4, q = id & 15;
        float4 v = reinterpret_cast<const float4*>(g_dist + (size_t)(m0 + r) * N_LEAF)[q];
        *reinterpret_cast<float4*>(Dt + r * 68 + q * 4) = v;
    }

    float O[2][4][4];
#pragma unroll
    for (int i = 0; i < 2; i++)
#pragma unroll
        for (int j = 0; j < 4; j++)
#pragma unroll
            for (int r = 0; r < 4; r++) O[i][j][r] = 0.f;

    // Prologue: prefetch B tiles for it=0 and it=1 into buffers 0, 1
    issue_b(sb + BOFF, 0, nb, tid);
    CP_COMMIT();
    issue_b(sb + BOFF + 8192, 1, nb, tid);
    CP_COMMIT();

    uint32_t A[4][2][4];

    for (int it = 0; it < 512; it++) {
        const int l = it & 63;

        CP_WAIT1();            // group 'it' landed (group it+1 may be in flight)
        __syncthreads();       // B buf[it%3] visible; buf[(it+2)%3] free; all past it-1

        if (l == 0) {
            // ---- rebuild X tile [64m x 64k] fp16 (half2 words, pitch 36) ----
            const float* xp = x + (size_t)m0 * D_DIM + (it >> 6) * 64;
#pragma unroll
            for (int e = 0; e < 8; e++) {
                int id = tid + e * 128;        // 0..1023 float4s (64 rows x 16)
                int m = id >> 4, q = id & 15;
                float4 v = *reinterpret_cast<const float4*>(xp + (size_t)m * D_DIM + q * 4);
                uint2 u = make_uint2(pack_h2(v.x, v.y), pack_h2(v.z, v.w));
                *reinterpret_cast<uint2*>(XW + m * 36 + q * 2) = u;
            }
            __syncthreads();
            // ---- A fragments into registers (held across the 64-leaf run) ----
#pragma unroll
            for (int ks = 0; ks < 4; ks++) {
#pragma unroll
                for (int i = 0; i < 2; i++) {
                    int m = wm * 32 + i * 16 + g;
                    int k = ks * 8 + tg;
                    A[ks][i][0] = XW[m * 36 + k];
                    A[ks][i][1] = XW[(m + 8) * 36 + k];
                    A[ks][i][2] = XW[m * 36 + k + 4];
                    A[ks][i][3] = XW[(m + 8) * 36 + k + 4];
                }
            }
        }

        // Prefetch B tile for it+2 into buffer (it+2)%3 (always commit)
        if (it + 2 < 512)
            issue_b(sb + BOFF + ((it + 2) % 3) * 8192, it + 2, nb, tid);
        CP_COMMIT();

        const char* Bb = sm + BOFF + (it % 3) * 8192 + wn * 4096;

        float P[2][4][4];
#pragma unroll
        for (int i = 0; i < 2; i++)
#pragma unroll
            for (int j = 0; j < 4; j++)
#pragma unroll
                for (int r = 0; r < 4; r++) P[i][j][r] = 0.f;

        uint4 c0 = *reinterpret_cast<const uint4*>(Bb + lane_sw0);
        uint4 c1 = *reinterpret_cast<const uint4*>(Bb + lane_sw1);
#pragma unroll
        for (int ks = 0; ks < 4; ks++) {
            uint4 n0_, n1_;
            if (ks < 3) {
                n0_ = *reinterpret_cast<const uint4*>(Bb + (ks + 1) * 1024 + lane_sw0);
                n1_ = *reinterpret_cast<const uint4*>(Bb + (ks + 1) * 1024 + lane_sw1);
            }
            uint32_t b[4][2];
            b[0][0] = c0.x; b[0][1] = c0.y;
            b[1][0] = c0.z; b[1][1] = c0.w;
            b[2][0] = c1.x; b[2][1] = c1.y;
            b[3][0] = c1.z; b[3][1] = c1.w;
#pragma unroll
            for (int i = 0; i < 2; i++)
#pragma unroll
                for (int j = 0; j < 4; j++)
                    mma_f16(P[i][j], A[ks][i], b[j]);
            c0 = n0_; c1 = n1_;
        }

        // Epilogue: O += d[row, l] * P
#pragma unroll
        for (int i = 0; i < 2; i++) {
            int r0 = wm * 32 + i * 16 + g;
            float d0 = Dt[r0 * 68 + l];
            float d1 = Dt[(r0 + 8) * 68 + l];
#pragma unroll
            for (int j = 0; j < 4; j++) {
                O[i][j][0] = fmaf(d0, P[i][j][0], O[i][j][0]);
                O[i][j][1] = fmaf(d0, P[i][j][1], O[i][j][1]);
                O[i][j][2] = fmaf(d1, P[i][j][2], O[i][j][2]);
                O[i][j][3] = fmaf(d1, P[i][j][3], O[i][j][3]);
            }
        }
    }

    // Write output fragments
#pragma unroll
    for (int i = 0; i < 2; i++) {
        int r0 = m0 + wm * 32 + i * 16 + g;
#pragma unroll
        for (int j = 0; j < 4; j++) {
            int col = n0 + wn * 32 + j * 8 + 2 * tg;
            float2 v0 = make_float2(O[i][j][0], O[i][j][1]);
            float2 v1 = make_float2(O[i][j][2], O[i][j][3]);
            *reinterpret_cast<float2*>(out + (size_t)r0 * W_DIM + col)       = v0;
            *reinterpret_cast<float2*>(out + (size_t)(r0 + 8) * W_DIM + col) = v1;
        }
    }
}

// ---------------------------------------------------------------------------
extern "C" void kernel_launch(void* const* d_in, const int* in_sizes, int n_in,
                              void* d_out, int out_size)
{
    const float* x   = (const float*)d_in[0];
    const float* ray = (const float*)d_in[1];
    const float* w_i = (const float*)d_in[2];
    const float* b_i = (const float*)d_in[3];
    const float* a_i = (const float*)d_in[4];
    const float* T   = (const float*)d_in[5];
    const int*   idx = (const int*)d_in[6];
    float* out = (float*)d_out;

    cudaFuncSetAttribute(gemm_f16_kernel,
                         cudaFuncAttributeMaxDynamicSharedMemorySize, SMEM_BYTES);

    convert_kernel<<<dim3(8, 8, 64), 256>>>(T);
    dist_kernel<<<B_ROWS / 8, 256>>>(x, ray, w_i, b_i, a_i, idx);
    gemm_f16_kernel<<<dim3(W_DIM / 64, B_ROWS / 64), 128, SMEM_BYTES>>>(x, out);
}